// round 2
// baseline (speedup 1.0000x reference)
#include <cuda_runtime.h>
#include <cuda_bf16.h>
#include <cstdint>

// AttentionBlock fused kernel, sm_103a.
// One CTA per (b,h) row: seq=64, c=256. All intermediates in SMEM.
// bf16 mma.sync tensor-core math, fp32 accumulation, fp32 residual.

#define SEQ   64
#define CH    256
#define LDH   264   // bf16 tile row stride in halves (528B: 16B-aligned, bank-conflict-free)
#define LDSS  68    // fp32 score tile stride (floats)
#define LDP   72    // bf16 P tile stride (144B, 16B-aligned)

// Pre-converted bf16 weights (scratch: __device__ globals, no allocation)
__device__ __nv_bfloat16 g_Wb[4][CH * CH];

__global__ void convw_kernel(const float* __restrict__ Wq, const float* __restrict__ Wk,
                             const float* __restrict__ Wv, const float* __restrict__ Wo) {
    int i = blockIdx.x * blockDim.x + threadIdx.x;
    if (i < CH * CH) {
        g_Wb[0][i] = __float2bfloat16(Wq[i]);
        g_Wb[1][i] = __float2bfloat16(Wk[i]);
        g_Wb[2][i] = __float2bfloat16(Wv[i]);
        g_Wb[3][i] = __float2bfloat16(Wo[i]);
    }
}

__device__ __forceinline__ uint32_t smem_u32(const void* p) {
    return (uint32_t)__cvta_generic_to_shared(p);
}

__device__ __forceinline__ void ldm_x4(uint32_t addr, uint32_t& a0, uint32_t& a1,
                                       uint32_t& a2, uint32_t& a3) {
    asm volatile("ldmatrix.sync.aligned.m8n8.x4.shared.b16 {%0,%1,%2,%3}, [%4];"
                 : "=r"(a0), "=r"(a1), "=r"(a2), "=r"(a3) : "r"(addr));
}
__device__ __forceinline__ void ldm_x2(uint32_t addr, uint32_t& b0, uint32_t& b1) {
    asm volatile("ldmatrix.sync.aligned.m8n8.x2.shared.b16 {%0,%1}, [%2];"
                 : "=r"(b0), "=r"(b1) : "r"(addr));
}
__device__ __forceinline__ void ldm_x2t(uint32_t addr, uint32_t& b0, uint32_t& b1) {
    asm volatile("ldmatrix.sync.aligned.m8n8.x2.trans.shared.b16 {%0,%1}, [%2];"
                 : "=r"(b0), "=r"(b1) : "r"(addr));
}
__device__ __forceinline__ void mma_bf16(float c[4],
                                         uint32_t a0, uint32_t a1, uint32_t a2, uint32_t a3,
                                         uint32_t b0, uint32_t b1) {
    asm volatile("mma.sync.aligned.m16n8k16.row.col.f32.bf16.bf16.f32 "
                 "{%0,%1,%2,%3}, {%4,%5,%6,%7}, {%8,%9}, {%0,%1,%2,%3};"
                 : "+f"(c[0]), "+f"(c[1]), "+f"(c[2]), "+f"(c[3])
                 : "r"(a0), "r"(a1), "r"(a2), "r"(a3), "r"(b0), "r"(b1));
}

// SMEM budget:
//   sX  64x264 bf16 = 33792   (x tile, later reused as O1 = P@V)
//   sQ  33792, sK 33792, sV 33792
//   sW  33792  (weight chunk [64][256]; fp32 score tile sS aliases this)
//   sP  64x72 bf16 = 9216
//   sBias 4*256 f32 = 4096
// total = 182272 bytes
#define SMEM_BYTES 182272

__global__ void __launch_bounds__(512, 1)
attn_kernel(const float* __restrict__ x,
            const float* __restrict__ bq, const float* __restrict__ bk,
            const float* __restrict__ bv, const float* __restrict__ bo,
            float* __restrict__ out)
{
    extern __shared__ char smem_raw[];
    __nv_bfloat16* sX = (__nv_bfloat16*)smem_raw;
    __nv_bfloat16* sQ = sX + SEQ * LDH;
    __nv_bfloat16* sK = sQ + SEQ * LDH;
    __nv_bfloat16* sV = sK + SEQ * LDH;
    __nv_bfloat16* sW = sV + SEQ * LDH;
    float*         sS = (float*)sW;                 // alias: scores live where W chunks do
    __nv_bfloat16* sP = sW + SEQ * LDH;
    float*      sBias = (float*)(sP + SEQ * LDP);

    const int tid  = threadIdx.x;
    const int wid  = tid >> 5;
    const int lane = tid & 31;
    const int grp  = lane >> 2;
    const int tig  = lane & 3;
    const int bh   = blockIdx.x;

    const float* xrow = x   + (size_t)bh * SEQ * CH;
    float*       orow = out + (size_t)bh * SEQ * CH;

    // ---------------- Phase 0: load biases + x tile (fp32 -> bf16) ----------------
    if (tid < CH) {
        sBias[tid]          = bq[tid];
        sBias[CH + tid]     = bk[tid];
        sBias[2 * CH + tid] = bv[tid];
        sBias[3 * CH + tid] = bo[tid];
    }
    {
        const float4* xv = (const float4*)xrow;
        #pragma unroll
        for (int t = 0; t < 8; t++) {
            int i = tid + t * 512;            // 4096 float4 total
            int row = i >> 6;
            int colf = (i & 63) * 4;
            float4 v = xv[i];
            __nv_bfloat162* d = (__nv_bfloat162*)(sX + row * LDH + colf);
            d[0] = __floats2bfloat162_rn(v.x, v.y);
            d[1] = __floats2bfloat162_rn(v.z, v.w);
        }
    }
    __syncthreads();

    const int rg = wid >> 2, cq = wid & 3;
    const int r0 = rg * 16;       // warp's 16 output rows
    const int nb = cq * 64;       // warp's 64 output cols (GEMM phases)

    // ---------------- Phase 2: Q/K/V = x @ W + b ----------------
    #pragma unroll 1
    for (int g = 0; g < 3; g++) {
        const uint4* Wg = (const uint4*)(g_Wb[g]);
        __nv_bfloat16* dst = (g == 0) ? sQ : (g == 1) ? sK : sV;
        float acc[8][4];
        #pragma unroll
        for (int nt = 0; nt < 8; nt++)
            acc[nt][0] = acc[nt][1] = acc[nt][2] = acc[nt][3] = 0.f;

        #pragma unroll 1
        for (int kc = 0; kc < 4; kc++) {
            // stream W chunk [64 k][256 n] bf16 into sW
            #pragma unroll
            for (int i = 0; i < 4; i++) {
                int j = tid + i * 512;        // 2048 uint4
                *(uint4*)(sW + (j >> 5) * LDH + (j & 31) * 8) = Wg[kc * 2048 + j];
            }
            __syncthreads();
            #pragma unroll
            for (int ks = 0; ks < 4; ks++) {
                uint32_t a0, a1, a2, a3;
                ldm_x4(smem_u32(sX + (r0 + (lane & 15)) * LDH
                                + kc * 64 + ks * 16 + ((lane >> 4) << 3)),
                       a0, a1, a2, a3);
                #pragma unroll
                for (int nt = 0; nt < 8; nt++) {
                    uint32_t b0, b1;
                    ldm_x2t(smem_u32(sW + (ks * 16 + (lane & 15)) * LDH + nb + nt * 8), b0, b1);
                    mma_bf16(acc[nt], a0, a1, a2, a3, b0, b1);
                }
            }
            __syncthreads();
        }
        // bias add + bf16 store
        #pragma unroll
        for (int nt = 0; nt < 8; nt++) {
            int col = nb + nt * 8 + tig * 2;
            float b0v = sBias[g * CH + col], b1v = sBias[g * CH + col + 1];
            *(__nv_bfloat162*)(dst + (r0 + grp) * LDH + col) =
                __floats2bfloat162_rn(acc[nt][0] + b0v, acc[nt][1] + b1v);
            *(__nv_bfloat162*)(dst + (r0 + grp + 8) * LDH + col) =
                __floats2bfloat162_rn(acc[nt][2] + b0v, acc[nt][3] + b1v);
        }
    }
    __syncthreads();

    // ---------------- Phase 3: S = (Q K^T) * scale ----------------
    {
        const int j0 = (wid & 3) * 16;    // 16 score cols per warp
        float sa[2][4] = {};
        #pragma unroll
        for (int ks = 0; ks < 16; ks++) {
            uint32_t a0, a1, a2, a3;
            ldm_x4(smem_u32(sQ + (r0 + (lane & 15)) * LDH + ks * 16 + ((lane >> 4) << 3)),
                   a0, a1, a2, a3);
            #pragma unroll
            for (int nt = 0; nt < 2; nt++) {
                uint32_t b0, b1;
                // B(k=c, n=j) = K[j][c]: non-trans ldmatrix on row-major K
                ldm_x2(smem_u32(sK + (j0 + nt * 8 + (lane & 7)) * LDH
                                + ks * 16 + (((lane >> 3) & 1) << 3)), b0, b1);
                mma_bf16(sa[nt], a0, a1, a2, a3, b0, b1);
            }
        }
        const float SCALE = 1.0f / (256.0f * 16.0f * 0.70710678118654752f);
        #pragma unroll
        for (int nt = 0; nt < 2; nt++) {
            int col = j0 + nt * 8 + tig * 2;
            sS[(r0 + grp) * LDSS + col]       = sa[nt][0] * SCALE;
            sS[(r0 + grp) * LDSS + col + 1]   = sa[nt][1] * SCALE;
            sS[(r0 + grp + 8) * LDSS + col]     = sa[nt][2] * SCALE;
            sS[(r0 + grp + 8) * LDSS + col + 1] = sa[nt][3] * SCALE;
        }
    }
    __syncthreads();

    // ---------------- Phase 4: softmax rows -> P (bf16) ----------------
    {
        int row = tid >> 3, s8 = tid & 7;      // 8 threads per row, 8 cols each
        const float* sr = sS + row * LDSS + s8 * 8;
        float v[8], e[8];
        #pragma unroll
        for (int i = 0; i < 8; i++) v[i] = sr[i];
        float m = v[0];
        #pragma unroll
        for (int i = 1; i < 8; i++) m = fmaxf(m, v[i]);
        #pragma unroll
        for (int d = 1; d < 8; d <<= 1) m = fmaxf(m, __shfl_xor_sync(0xffffffffu, m, d));
        float s = 0.f;
        #pragma unroll
        for (int i = 0; i < 8; i++) { e[i] = __expf(v[i] - m); s += e[i]; }
        #pragma unroll
        for (int d = 1; d < 8; d <<= 1) s += __shfl_xor_sync(0xffffffffu, s, d);
        float inv = 1.0f / s;
        __nv_bfloat162* dp = (__nv_bfloat162*)(sP + row * LDP + s8 * 8);
        #pragma unroll
        for (int i = 0; i < 4; i++)
            dp[i] = __floats2bfloat162_rn(e[2 * i] * inv, e[2 * i + 1] * inv);
    }
    __syncthreads();

    // ---------------- Phase 5: O1 = P @ V  (stored into sX) ----------------
    {
        float acc[8][4] = {};
        #pragma unroll
        for (int ks = 0; ks < 4; ks++) {
            uint32_t a0, a1, a2, a3;
            ldm_x4(smem_u32(sP + (r0 + (lane & 15)) * LDP + ks * 16 + ((lane >> 4) << 3)),
                   a0, a1, a2, a3);
            #pragma unroll
            for (int nt = 0; nt < 8; nt++) {
                uint32_t b0, b1;
                ldm_x2t(smem_u32(sV + (ks * 16 + (lane & 15)) * LDH + nb + nt * 8), b0, b1);
                mma_bf16(acc[nt], a0, a1, a2, a3, b0, b1);
            }
        }
        #pragma unroll
        for (int nt = 0; nt < 8; nt++) {
            int col = nb + nt * 8 + tig * 2;
            *(__nv_bfloat162*)(sX + (r0 + grp) * LDH + col) =
                __floats2bfloat162_rn(acc[nt][0], acc[nt][1]);
            *(__nv_bfloat162*)(sX + (r0 + grp + 8) * LDH + col) =
                __floats2bfloat162_rn(acc[nt][2], acc[nt][3]);
        }
    }
    __syncthreads();

    // ---------------- Phase 6: out = O1 @ Wo + bo + x ----------------
    {
        const uint4* Wg = (const uint4*)(g_Wb[3]);
        float acc[8][4] = {};
        #pragma unroll 1
        for (int kc = 0; kc < 4; kc++) {
            #pragma unroll
            for (int i = 0; i < 4; i++) {
                int j = tid + i * 512;
                *(uint4*)(sW + (j >> 5) * LDH + (j & 31) * 8) = Wg[kc * 2048 + j];
            }
            __syncthreads();
            #pragma unroll
            for (int ks = 0; ks < 4; ks++) {
                uint32_t a0, a1, a2, a3;
                ldm_x4(smem_u32(sX + (r0 + (lane & 15)) * LDH
                                + kc * 64 + ks * 16 + ((lane >> 4) << 3)),
                       a0, a1, a2, a3);
                #pragma unroll
                for (int nt = 0; nt < 8; nt++) {
                    uint32_t b0, b1;
                    ldm_x2t(smem_u32(sW + (ks * 16 + (lane & 15)) * LDH + nb + nt * 8), b0, b1);
                    mma_bf16(acc[nt], a0, a1, a2, a3, b0, b1);
                }
            }
            __syncthreads();
        }
        #pragma unroll
        for (int nt = 0; nt < 8; nt++) {
            int col = nb + nt * 8 + tig * 2;
            float b0v = sBias[3 * CH + col], b1v = sBias[3 * CH + col + 1];
            int ra = r0 + grp, rb = ra + 8;
            float2 xa = *(const float2*)(xrow + ra * CH + col);
            float2 xb = *(const float2*)(xrow + rb * CH + col);
            *(float2*)(orow + ra * CH + col) =
                make_float2(acc[nt][0] + b0v + xa.x, acc[nt][1] + b1v + xa.y);
            *(float2*)(orow + rb * CH + col) =
                make_float2(acc[nt][2] + b0v + xb.x, acc[nt][3] + b1v + xb.y);
        }
    }
}

extern "C" void kernel_launch(void* const* d_in, const int* in_sizes, int n_in,
                              void* d_out, int out_size) {
    const float* x  = (const float*)d_in[0];
    const float* Wq = (const float*)d_in[1];
    const float* bq = (const float*)d_in[2];
    const float* Wk = (const float*)d_in[3];
    const float* bk = (const float*)d_in[4];
    const float* Wv = (const float*)d_in[5];
    const float* bv = (const float*)d_in[6];
    const float* Wo = (const float*)d_in[7];
    const float* bo = (const float*)d_in[8];
    float* out = (float*)d_out;

    convw_kernel<<<256, 256>>>(Wq, Wk, Wv, Wo);

    // Idempotent; harness's correctness run sets it before capture too.
    cudaFuncSetAttribute(attn_kernel, cudaFuncAttributeMaxDynamicSharedMemorySize, SMEM_BYTES);
    attn_kernel<<<2048, 512, SMEM_BYTES>>>(x, bq, bk, bv, bo, out);
}

// round 3
// speedup vs baseline: 1.2285x; 1.2285x over previous
#include <cuda_runtime.h>
#include <cuda_bf16.h>
#include <cstdint>

// AttentionBlock fused kernel, sm_103a. Round 2:
// 256 threads, 32x64 warp tiles (192 B smem / mma vs 320 before),
// ldmatrix.x4.trans for B, cp.async double-buffered weight streaming.

#define SEQ   64
#define CH    256
#define LDH   264   // bf16 tile row stride in halves
#define LDSS  68    // fp32 score tile stride (floats)
#define LDP   72    // bf16 P tile stride

__device__ __nv_bfloat16 g_Wb[4][CH * CH];

__global__ void convw_kernel(const float* __restrict__ Wq, const float* __restrict__ Wk,
                             const float* __restrict__ Wv, const float* __restrict__ Wo) {
    int i = blockIdx.x * blockDim.x + threadIdx.x;
    if (i < CH * CH) {
        g_Wb[0][i] = __float2bfloat16(Wq[i]);
        g_Wb[1][i] = __float2bfloat16(Wk[i]);
        g_Wb[2][i] = __float2bfloat16(Wv[i]);
        g_Wb[3][i] = __float2bfloat16(Wo[i]);
    }
}

__device__ __forceinline__ uint32_t smem_u32(const void* p) {
    return (uint32_t)__cvta_generic_to_shared(p);
}
__device__ __forceinline__ void ldm_x4(uint32_t addr, uint32_t& a0, uint32_t& a1,
                                       uint32_t& a2, uint32_t& a3) {
    asm volatile("ldmatrix.sync.aligned.m8n8.x4.shared.b16 {%0,%1,%2,%3}, [%4];"
                 : "=r"(a0), "=r"(a1), "=r"(a2), "=r"(a3) : "r"(addr));
}
__device__ __forceinline__ void ldm_x4t(uint32_t addr, uint32_t& b0, uint32_t& b1,
                                        uint32_t& b2, uint32_t& b3) {
    asm volatile("ldmatrix.sync.aligned.m8n8.x4.trans.shared.b16 {%0,%1,%2,%3}, [%4];"
                 : "=r"(b0), "=r"(b1), "=r"(b2), "=r"(b3) : "r"(addr));
}
__device__ __forceinline__ void mma_bf16(float c[4],
                                         uint32_t a0, uint32_t a1, uint32_t a2, uint32_t a3,
                                         uint32_t b0, uint32_t b1) {
    asm volatile("mma.sync.aligned.m16n8k16.row.col.f32.bf16.bf16.f32 "
                 "{%0,%1,%2,%3}, {%4,%5,%6,%7}, {%8,%9}, {%0,%1,%2,%3};"
                 : "+f"(c[0]), "+f"(c[1]), "+f"(c[2]), "+f"(c[3])
                 : "r"(a0), "r"(a1), "r"(a2), "r"(a3), "r"(b0), "r"(b1));
}
__device__ __forceinline__ void cp16(void* smem, const void* gmem) {
    asm volatile("cp.async.cg.shared.global [%0], [%1], 16;"
                 :: "r"(smem_u32(smem)), "l"(gmem));
}

// Stream a [64 k][256 n] bf16 weight chunk into smem (strided LDH rows).
__device__ __forceinline__ void load_w_chunk(__nv_bfloat16* dst,
                                             const __nv_bfloat16* src, int tid) {
    #pragma unroll
    for (int i = 0; i < 8; i++) {
        int j = tid + i * 256;     // 2048 x 16B
        cp16(dst + (j >> 5) * LDH + (j & 31) * 8, src + j * 8);
    }
    asm volatile("cp.async.commit_group;");
}

// SMEM: sX,sQ,sK,sV (4*33792) + sW0,sW1 (2*33792) + sP 9216 + sBias 4096 = 216064
#define SMEM_BYTES 216064

__global__ void __launch_bounds__(256, 1)
attn_kernel(const float* __restrict__ x,
            const float* __restrict__ bq, const float* __restrict__ bk,
            const float* __restrict__ bv, const float* __restrict__ bo,
            float* __restrict__ out)
{
    extern __shared__ char smem_raw[];
    __nv_bfloat16* sX = (__nv_bfloat16*)smem_raw;
    __nv_bfloat16* sQ = sX + SEQ * LDH;
    __nv_bfloat16* sK = sQ + SEQ * LDH;
    __nv_bfloat16* sV = sK + SEQ * LDH;
    __nv_bfloat16* sW0 = sV + SEQ * LDH;
    __nv_bfloat16* sW1 = sW0 + SEQ * LDH;
    float*         sS = (float*)sW0;              // scores alias W buffer 0
    __nv_bfloat16* sP = sW1 + SEQ * LDH;
    float*      sBias = (float*)(sP + SEQ * LDP);

    const int tid  = threadIdx.x;
    const int wid  = tid >> 5;
    const int lane = tid & 31;
    const int grp  = lane >> 2;
    const int tig  = lane & 3;
    const int bh   = blockIdx.x;

    const float* xrow = x   + (size_t)bh * SEQ * CH;
    float*       orow = out + (size_t)bh * SEQ * CH;

    // ---------------- Phase 0: biases + x tile (fp32 -> bf16) ----------------
    sBias[tid]          = bq[tid];
    sBias[CH + tid]     = bk[tid];
    sBias[2 * CH + tid] = bv[tid];
    sBias[3 * CH + tid] = bo[tid];
    {
        const float4* xv = (const float4*)xrow;
        #pragma unroll
        for (int t = 0; t < 16; t++) {
            int i = tid + t * 256;             // 4096 float4
            int row = i >> 6;
            int colf = (i & 63) * 4;
            float4 v = xv[i];
            __nv_bfloat162* d = (__nv_bfloat162*)(sX + row * LDH + colf);
            d[0] = __floats2bfloat162_rn(v.x, v.y);
            d[1] = __floats2bfloat162_rn(v.z, v.w);
        }
    }
    __syncthreads();

    const int rg = wid >> 2, cq = wid & 3;
    const int r0 = rg * 32;       // warp's 32 output rows
    const int nb = cq * 64;       // warp's 64 output cols

    // ---------------- Phase 2: Q/K/V = x @ W + b ----------------
    #pragma unroll 1
    for (int g = 0; g < 3; g++) {
        const __nv_bfloat16* Wg = g_Wb[g];
        __nv_bfloat16* dst = (g == 0) ? sQ : (g == 1) ? sK : sV;
        float acc[2][8][4] = {};

        load_w_chunk(sW0, Wg, tid);
        #pragma unroll 1
        for (int kc = 0; kc < 4; kc++) {
            __nv_bfloat16* wbuf = (kc & 1) ? sW1 : sW0;
            if (kc < 3) {
                load_w_chunk((kc & 1) ? sW0 : sW1, Wg + (kc + 1) * 64 * CH, tid);
                asm volatile("cp.async.wait_group 1;");
            } else {
                asm volatile("cp.async.wait_group 0;");
            }
            __syncthreads();
            #pragma unroll
            for (int ks = 0; ks < 4; ks++) {
                uint32_t a[2][4];
                #pragma unroll
                for (int mt = 0; mt < 2; mt++)
                    ldm_x4(smem_u32(sX + (r0 + mt * 16 + (lane & 15)) * LDH
                                    + kc * 64 + ks * 16 + ((lane >> 4) << 3)),
                           a[mt][0], a[mt][1], a[mt][2], a[mt][3]);
                #pragma unroll
                for (int nt16 = 0; nt16 < 4; nt16++) {
                    uint32_t b0, b1, b2, b3;
                    ldm_x4t(smem_u32(wbuf + (ks * 16 + (lane & 15)) * LDH
                                     + nb + nt16 * 16 + ((lane >> 4) << 3)),
                            b0, b1, b2, b3);
                    #pragma unroll
                    for (int mt = 0; mt < 2; mt++) {
                        mma_bf16(acc[mt][2 * nt16],     a[mt][0], a[mt][1], a[mt][2], a[mt][3], b0, b1);
                        mma_bf16(acc[mt][2 * nt16 + 1], a[mt][0], a[mt][1], a[mt][2], a[mt][3], b2, b3);
                    }
                }
            }
            __syncthreads();
        }
        #pragma unroll
        for (int mt = 0; mt < 2; mt++)
            #pragma unroll
            for (int nt = 0; nt < 8; nt++) {
                int col = nb + nt * 8 + tig * 2;
                float b0v = sBias[g * CH + col], b1v = sBias[g * CH + col + 1];
                int ra = r0 + mt * 16 + grp;
                *(__nv_bfloat162*)(dst + ra * LDH + col) =
                    __floats2bfloat162_rn(acc[mt][nt][0] + b0v, acc[mt][nt][1] + b1v);
                *(__nv_bfloat162*)(dst + (ra + 8) * LDH + col) =
                    __floats2bfloat162_rn(acc[mt][nt][2] + b0v, acc[mt][nt][3] + b1v);
            }
    }
    __syncthreads();

    // ---------------- Phase 3: S = (Q K^T) * scale ----------------
    {
        const int rw = wid >> 1, cs = wid & 1;
        const int r0s = rw * 16, j0 = cs * 32;
        float sa[4][4] = {};
        #pragma unroll
        for (int ks = 0; ks < 16; ks++) {
            uint32_t a0, a1, a2, a3;
            ldm_x4(smem_u32(sQ + (r0s + (lane & 15)) * LDH + ks * 16 + ((lane >> 4) << 3)),
                   a0, a1, a2, a3);
            #pragma unroll
            for (int nt16 = 0; nt16 < 2; nt16++) {
                uint32_t b0, b1, b2, b3;
                // non-trans x4 on row-major K: (m0,m1)=(k0-7,k8-15) of ntile, (m2,m3)=ntile+1
                ldm_x4(smem_u32(sK + (j0 + nt16 * 16 + ((lane >> 4) << 3) + (lane & 7)) * LDH
                                + ks * 16 + (((lane >> 3) & 1) << 3)),
                       b0, b1, b2, b3);
                mma_bf16(sa[2 * nt16],     a0, a1, a2, a3, b0, b1);
                mma_bf16(sa[2 * nt16 + 1], a0, a1, a2, a3, b2, b3);
            }
        }
        const float SCALE = 1.0f / (256.0f * 16.0f * 0.70710678118654752f);
        #pragma unroll
        for (int nt = 0; nt < 4; nt++) {
            int col = j0 + nt * 8 + tig * 2;
            sS[(r0s + grp) * LDSS + col]         = sa[nt][0] * SCALE;
            sS[(r0s + grp) * LDSS + col + 1]     = sa[nt][1] * SCALE;
            sS[(r0s + grp + 8) * LDSS + col]     = sa[nt][2] * SCALE;
            sS[(r0s + grp + 8) * LDSS + col + 1] = sa[nt][3] * SCALE;
        }
    }
    __syncthreads();

    // ---------------- Phase 4: softmax rows -> P (bf16) ----------------
    {
        int row = tid >> 2, t4 = tid & 3;     // 4 threads per row, 16 cols each
        const float* sr = sS + row * LDSS + t4 * 16;
        float v[16], e[16];
        #pragma unroll
        for (int i = 0; i < 16; i++) v[i] = sr[i];
        float m = v[0];
        #pragma unroll
        for (int i = 1; i < 16; i++) m = fmaxf(m, v[i]);
        m = fmaxf(m, __shfl_xor_sync(0xffffffffu, m, 1));
        m = fmaxf(m, __shfl_xor_sync(0xffffffffu, m, 2));
        float s = 0.f;
        #pragma unroll
        for (int i = 0; i < 16; i++) { e[i] = __expf(v[i] - m); s += e[i]; }
        s += __shfl_xor_sync(0xffffffffu, s, 1);
        s += __shfl_xor_sync(0xffffffffu, s, 2);
        float inv = 1.0f / s;
        __nv_bfloat162* dp = (__nv_bfloat162*)(sP + row * LDP + t4 * 16);
        #pragma unroll
        for (int i = 0; i < 8; i++)
            dp[i] = __floats2bfloat162_rn(e[2 * i] * inv, e[2 * i + 1] * inv);
    }
    __syncthreads();

    // ---------------- Phase 5: O1 = P @ V (stored into sX) ----------------
    {
        float acc[2][8][4] = {};
        #pragma unroll
        for (int ks = 0; ks < 4; ks++) {
            uint32_t a[2][4];
            #pragma unroll
            for (int mt = 0; mt < 2; mt++)
                ldm_x4(smem_u32(sP + (r0 + mt * 16 + (lane & 15)) * LDP
                                + ks * 16 + ((lane >> 4) << 3)),
                       a[mt][0], a[mt][1], a[mt][2], a[mt][3]);
            #pragma unroll
            for (int nt16 = 0; nt16 < 4; nt16++) {
                uint32_t b0, b1, b2, b3;
                ldm_x4t(smem_u32(sV + (ks * 16 + (lane & 15)) * LDH
                                 + nb + nt16 * 16 + ((lane >> 4) << 3)),
                        b0, b1, b2, b3);
                #pragma unroll
                for (int mt = 0; mt < 2; mt++) {
                    mma_bf16(acc[mt][2 * nt16],     a[mt][0], a[mt][1], a[mt][2], a[mt][3], b0, b1);
                    mma_bf16(acc[mt][2 * nt16 + 1], a[mt][0], a[mt][1], a[mt][2], a[mt][3], b2, b3);
                }
            }
        }
        __syncthreads();   // phase 3/4 consumers done before sX overwrite? (sX re-written below)
        #pragma unroll
        for (int mt = 0; mt < 2; mt++)
            #pragma unroll
            for (int nt = 0; nt < 8; nt++) {
                int col = nb + nt * 8 + tig * 2;
                int ra = r0 + mt * 16 + grp;
                *(__nv_bfloat162*)(sX + ra * LDH + col) =
                    __floats2bfloat162_rn(acc[mt][nt][0], acc[mt][nt][1]);
                *(__nv_bfloat162*)(sX + (ra + 8) * LDH + col) =
                    __floats2bfloat162_rn(acc[mt][nt][2], acc[mt][nt][3]);
            }
    }
    __syncthreads();

    // ---------------- Phase 6: out = O1 @ Wo + bo + x ----------------
    {
        const __nv_bfloat16* Wg = g_Wb[3];
        float acc[2][8][4] = {};
        load_w_chunk(sW0, Wg, tid);
        #pragma unroll 1
        for (int kc = 0; kc < 4; kc++) {
            __nv_bfloat16* wbuf = (kc & 1) ? sW1 : sW0;
            if (kc < 3) {
                load_w_chunk((kc & 1) ? sW0 : sW1, Wg + (kc + 1) * 64 * CH, tid);
                asm volatile("cp.async.wait_group 1;");
            } else {
                asm volatile("cp.async.wait_group 0;");
            }
            __syncthreads();
            #pragma unroll
            for (int ks = 0; ks < 4; ks++) {
                uint32_t a[2][4];
                #pragma unroll
                for (int mt = 0; mt < 2; mt++)
                    ldm_x4(smem_u32(sX + (r0 + mt * 16 + (lane & 15)) * LDH
                                    + kc * 64 + ks * 16 + ((lane >> 4) << 3)),
                           a[mt][0], a[mt][1], a[mt][2], a[mt][3]);
                #pragma unroll
                for (int nt16 = 0; nt16 < 4; nt16++) {
                    uint32_t b0, b1, b2, b3;
                    ldm_x4t(smem_u32(wbuf + (ks * 16 + (lane & 15)) * LDH
                                     + nb + nt16 * 16 + ((lane >> 4) << 3)),
                            b0, b1, b2, b3);
                    #pragma unroll
                    for (int mt = 0; mt < 2; mt++) {
                        mma_bf16(acc[mt][2 * nt16],     a[mt][0], a[mt][1], a[mt][2], a[mt][3], b0, b1);
                        mma_bf16(acc[mt][2 * nt16 + 1], a[mt][0], a[mt][1], a[mt][2], a[mt][3], b2, b3);
                    }
                }
            }
            __syncthreads();
        }
        #pragma unroll
        for (int mt = 0; mt < 2; mt++)
            #pragma unroll
            for (int nt = 0; nt < 8; nt++) {
                int col = nb + nt * 8 + tig * 2;
                float b0v = sBias[3 * CH + col], b1v = sBias[3 * CH + col + 1];
                int ra = r0 + mt * 16 + grp, rb = ra + 8;
                float2 xa = *(const float2*)(xrow + ra * CH + col);
                float2 xb = *(const float2*)(xrow + rb * CH + col);
                *(float2*)(orow + ra * CH + col) =
                    make_float2(acc[mt][nt][0] + b0v + xa.x, acc[mt][nt][1] + b1v + xa.y);
                *(float2*)(orow + rb * CH + col) =
                    make_float2(acc[mt][nt][2] + b0v + xb.x, acc[mt][nt][3] + b1v + xb.y);
            }
    }
}

extern "C" void kernel_launch(void* const* d_in, const int* in_sizes, int n_in,
                              void* d_out, int out_size) {
    const float* x  = (const float*)d_in[0];
    const float* Wq = (const float*)d_in[1];
    const float* bq = (const float*)d_in[2];
    const float* Wk = (const float*)d_in[3];
    const float* bk = (const float*)d_in[4];
    const float* Wv = (const float*)d_in[5];
    const float* bv = (const float*)d_in[6];
    const float* Wo = (const float*)d_in[7];
    const float* bo = (const float*)d_in[8];
    float* out = (float*)d_out;

    convw_kernel<<<256, 256>>>(Wq, Wk, Wv, Wo);

    cudaFuncSetAttribute(attn_kernel, cudaFuncAttributeMaxDynamicSharedMemorySize, SMEM_BYTES);
    attn_kernel<<<2048, 256, SMEM_BYTES>>>(x, bq, bk, bv, bo, out);
}

// round 4
// speedup vs baseline: 1.5786x; 1.2849x over previous
#include <cuda_runtime.h>
#include <cuda_bf16.h>
#include <cstdint>

// AttentionBlock fused kernel, sm_103a. Round 3:
// 2 CTAs/SM (smem 114688B), V eliminated via O1=(P@X)Wv+bv, Q parked in the
// W-staging buffer, in-register softmax, 32-row double-buffered cp.async W.

#define SEQ   64
#define CH    256
#define LDH   264   // bf16 tile row stride in halves
#define LDP   72    // bf16 P tile stride

__device__ __nv_bfloat16 g_Wb[4][CH * CH];

__global__ void convw_kernel(const float* __restrict__ Wq, const float* __restrict__ Wk,
                             const float* __restrict__ Wv, const float* __restrict__ Wo) {
    int i = blockIdx.x * blockDim.x + threadIdx.x;
    if (i < CH * CH) {
        g_Wb[0][i] = __float2bfloat16(Wq[i]);
        g_Wb[1][i] = __float2bfloat16(Wk[i]);
        g_Wb[2][i] = __float2bfloat16(Wv[i]);
        g_Wb[3][i] = __float2bfloat16(Wo[i]);
    }
}

__device__ __forceinline__ uint32_t smem_u32(const void* p) {
    return (uint32_t)__cvta_generic_to_shared(p);
}
__device__ __forceinline__ void ldm_x4(uint32_t addr, uint32_t& a0, uint32_t& a1,
                                       uint32_t& a2, uint32_t& a3) {
    asm volatile("ldmatrix.sync.aligned.m8n8.x4.shared.b16 {%0,%1,%2,%3}, [%4];"
                 : "=r"(a0), "=r"(a1), "=r"(a2), "=r"(a3) : "r"(addr));
}
__device__ __forceinline__ void ldm_x4t(uint32_t addr, uint32_t& b0, uint32_t& b1,
                                        uint32_t& b2, uint32_t& b3) {
    asm volatile("ldmatrix.sync.aligned.m8n8.x4.trans.shared.b16 {%0,%1,%2,%3}, [%4];"
                 : "=r"(b0), "=r"(b1), "=r"(b2), "=r"(b3) : "r"(addr));
}
__device__ __forceinline__ void mma_bf16(float c[4],
                                         uint32_t a0, uint32_t a1, uint32_t a2, uint32_t a3,
                                         uint32_t b0, uint32_t b1) {
    asm volatile("mma.sync.aligned.m16n8k16.row.col.f32.bf16.bf16.f32 "
                 "{%0,%1,%2,%3}, {%4,%5,%6,%7}, {%8,%9}, {%0,%1,%2,%3};"
                 : "+f"(c[0]), "+f"(c[1]), "+f"(c[2]), "+f"(c[3])
                 : "r"(a0), "r"(a1), "r"(a2), "r"(a3), "r"(b0), "r"(b1));
}
__device__ __forceinline__ void cp16(void* smem, const void* gmem) {
    asm volatile("cp.async.cg.shared.global [%0], [%1], 16;"
                 :: "r"(smem_u32(smem)), "l"(gmem));
}

// Stream a [32 k][256 n] bf16 weight chunk into smem (strided LDH rows).
__device__ __forceinline__ void load_w_chunk32(__nv_bfloat16* dst,
                                               const __nv_bfloat16* src, int tid) {
    #pragma unroll
    for (int i = 0; i < 4; i++) {
        int j = tid + i * 256;     // 1024 x 16B
        cp16(dst + (j >> 5) * LDH + (j & 31) * 8, src + j * 8);
    }
    asm volatile("cp.async.commit_group;");
}

// Core chunked GEMM: acc[32x64 warp tile] += A[64x256](smem) @ W[256x256](gmem).
__device__ __forceinline__ void gemm_w(const __nv_bfloat16* __restrict__ Wg,
                                       const __nv_bfloat16* sA, int ldA,
                                       __nv_bfloat16* sW0, __nv_bfloat16* sW1,
                                       float acc[2][8][4],
                                       int tid, int lane, int r0, int nb) {
    #pragma unroll
    for (int mt = 0; mt < 2; mt++)
        #pragma unroll
        for (int nt = 0; nt < 8; nt++)
            acc[mt][nt][0] = acc[mt][nt][1] = acc[mt][nt][2] = acc[mt][nt][3] = 0.f;

    load_w_chunk32(sW0, Wg, tid);
    #pragma unroll 1
    for (int kc = 0; kc < 8; kc++) {
        __nv_bfloat16* wbuf = (kc & 1) ? sW1 : sW0;
        if (kc < 7) {
            load_w_chunk32((kc & 1) ? sW0 : sW1, Wg + (kc + 1) * 32 * CH, tid);
            asm volatile("cp.async.wait_group 1;");
        } else {
            asm volatile("cp.async.wait_group 0;");
        }
        __syncthreads();
        #pragma unroll
        for (int ks = 0; ks < 2; ks++) {
            int kof = kc * 32 + ks * 16;
            uint32_t a[2][4];
            #pragma unroll
            for (int mt = 0; mt < 2; mt++)
                ldm_x4(smem_u32(sA + (r0 + mt * 16 + (lane & 15)) * ldA
                                + kof + ((lane >> 4) << 3)),
                       a[mt][0], a[mt][1], a[mt][2], a[mt][3]);
            #pragma unroll
            for (int nt16 = 0; nt16 < 4; nt16++) {
                uint32_t b0, b1, b2, b3;
                ldm_x4t(smem_u32(wbuf + (ks * 16 + (lane & 15)) * LDH
                                 + nb + nt16 * 16 + ((lane >> 4) << 3)),
                        b0, b1, b2, b3);
                #pragma unroll
                for (int mt = 0; mt < 2; mt++) {
                    mma_bf16(acc[mt][2 * nt16],     a[mt][0], a[mt][1], a[mt][2], a[mt][3], b0, b1);
                    mma_bf16(acc[mt][2 * nt16 + 1], a[mt][0], a[mt][1], a[mt][2], a[mt][3], b2, b3);
                }
            }
        }
        __syncthreads();
    }
}

// SMEM: sX 33792 + sK 33792 + sW0+sW1 (=sQ) 33792 + sP 9216 + bias 4096 = 114688
#define SMEM_BYTES 114688

__global__ void __launch_bounds__(256, 2)
attn_kernel(const float* __restrict__ x,
            const float* __restrict__ bq, const float* __restrict__ bk,
            const float* __restrict__ bv, const float* __restrict__ bo,
            float* __restrict__ out)
{
    extern __shared__ char smem_raw[];
    __nv_bfloat16* sX  = (__nv_bfloat16*)smem_raw;
    __nv_bfloat16* sK  = sX + SEQ * LDH;
    __nv_bfloat16* sW0 = sK + SEQ * LDH;
    __nv_bfloat16* sW1 = sW0 + 32 * LDH;
    __nv_bfloat16* sQ  = sW0;                     // Q parks over the W buffers
    __nv_bfloat16* sP  = sW1 + 32 * LDH;
    float*      sBias  = (float*)(sP + SEQ * LDP);

    const int tid  = threadIdx.x;
    const int wid  = tid >> 5;
    const int lane = tid & 31;
    const int grp  = lane >> 2;
    const int tig  = lane & 3;
    const int bh   = blockIdx.x;

    const float* xrow = x   + (size_t)bh * SEQ * CH;
    float*       orow = out + (size_t)bh * SEQ * CH;

    // ---------------- Phase 0: biases + x tile (fp32 -> bf16) ----------------
    sBias[tid]          = bq[tid];
    sBias[CH + tid]     = bk[tid];
    sBias[2 * CH + tid] = bv[tid];
    sBias[3 * CH + tid] = bo[tid];
    {
        const float4* xv = (const float4*)xrow;
        #pragma unroll
        for (int t = 0; t < 16; t++) {
            int i = tid + t * 256;             // 4096 float4
            int row = i >> 6;
            int colf = (i & 63) * 4;
            float4 v = xv[i];
            __nv_bfloat162* d = (__nv_bfloat162*)(sX + row * LDH + colf);
            d[0] = __floats2bfloat162_rn(v.x, v.y);
            d[1] = __floats2bfloat162_rn(v.z, v.w);
        }
    }
    __syncthreads();

    const int r0 = (wid >> 2) * 32;   // warp's 32 rows (GEMM tiling)
    const int nb = (wid & 3) * 64;    // warp's 64 cols

    float acc[2][8][4];

    // ---------------- K = X @ Wk + bk -> sK ----------------
    gemm_w(g_Wb[1], sX, LDH, sW0, sW1, acc, tid, lane, r0, nb);
    #pragma unroll
    for (int mt = 0; mt < 2; mt++)
        #pragma unroll
        for (int nt = 0; nt < 8; nt++) {
            int col = nb + nt * 8 + tig * 2;
            float b0v = sBias[CH + col], b1v = sBias[CH + col + 1];
            int ra = r0 + mt * 16 + grp;
            *(__nv_bfloat162*)(sK + ra * LDH + col) =
                __floats2bfloat162_rn(acc[mt][nt][0] + b0v, acc[mt][nt][1] + b1v);
            *(__nv_bfloat162*)(sK + (ra + 8) * LDH + col) =
                __floats2bfloat162_rn(acc[mt][nt][2] + b0v, acc[mt][nt][3] + b1v);
        }
    // no sync needed here: gemm_w ends with one, K readers sync below

    // ---------------- Q = X @ Wq + bq -> sQ (over W buffers) ----------------
    gemm_w(g_Wb[0], sX, LDH, sW0, sW1, acc, tid, lane, r0, nb);
    // gemm_w's final __syncthreads: all warps done reading Wq chunks AND all
    // K stores are visible. Now safe to overwrite the W region with Q.
    #pragma unroll
    for (int mt = 0; mt < 2; mt++)
        #pragma unroll
        for (int nt = 0; nt < 8; nt++) {
            int col = nb + nt * 8 + tig * 2;
            float b0v = sBias[col], b1v = sBias[col + 1];
            int ra = r0 + mt * 16 + grp;
            *(__nv_bfloat162*)(sQ + ra * LDH + col) =
                __floats2bfloat162_rn(acc[mt][nt][0] + b0v, acc[mt][nt][1] + b1v);
            *(__nv_bfloat162*)(sQ + (ra + 8) * LDH + col) =
                __floats2bfloat162_rn(acc[mt][nt][2] + b0v, acc[mt][nt][3] + b1v);
        }
    __syncthreads();

    // ---------------- S = (Q K^T)*scale, softmax -> P (warps 0-3, in-reg) ----
    if (wid < 4) {
        const int r0s = wid * 16;     // 16 rows, all 64 cols
        float sa[8][4];
        #pragma unroll
        for (int nt = 0; nt < 8; nt++)
            sa[nt][0] = sa[nt][1] = sa[nt][2] = sa[nt][3] = 0.f;
        #pragma unroll
        for (int ks = 0; ks < 16; ks++) {
            uint32_t a0, a1, a2, a3;
            ldm_x4(smem_u32(sQ + (r0s + (lane & 15)) * LDH + ks * 16 + ((lane >> 4) << 3)),
                   a0, a1, a2, a3);
            #pragma unroll
            for (int nt16 = 0; nt16 < 4; nt16++) {
                uint32_t b0, b1, b2, b3;
                // non-trans x4 on row-major K -> col-major B frags for 2 n-tiles
                ldm_x4(smem_u32(sK + (nt16 * 16 + ((lane >> 4) << 3) + (lane & 7)) * LDH
                                + ks * 16 + (((lane >> 3) & 1) << 3)),
                       b0, b1, b2, b3);
                mma_bf16(sa[2 * nt16],     a0, a1, a2, a3, b0, b1);
                mma_bf16(sa[2 * nt16 + 1], a0, a1, a2, a3, b2, b3);
            }
        }
        const float SCALE = 1.0f / (256.0f * 16.0f * 0.70710678118654752f);
        // row grp -> sa[nt][0..1], row grp+8 -> sa[nt][2..3]
        float v0[16], v1[16];
        #pragma unroll
        for (int nt = 0; nt < 8; nt++) {
            v0[2 * nt] = sa[nt][0] * SCALE; v0[2 * nt + 1] = sa[nt][1] * SCALE;
            v1[2 * nt] = sa[nt][2] * SCALE; v1[2 * nt + 1] = sa[nt][3] * SCALE;
        }
        float m0 = v0[0], m1 = v1[0];
        #pragma unroll
        for (int i = 1; i < 16; i++) { m0 = fmaxf(m0, v0[i]); m1 = fmaxf(m1, v1[i]); }
        m0 = fmaxf(m0, __shfl_xor_sync(0xffffffffu, m0, 1));
        m0 = fmaxf(m0, __shfl_xor_sync(0xffffffffu, m0, 2));
        m1 = fmaxf(m1, __shfl_xor_sync(0xffffffffu, m1, 1));
        m1 = fmaxf(m1, __shfl_xor_sync(0xffffffffu, m1, 2));
        float s0 = 0.f, s1 = 0.f;
        #pragma unroll
        for (int i = 0; i < 16; i++) {
            v0[i] = __expf(v0[i] - m0); s0 += v0[i];
            v1[i] = __expf(v1[i] - m1); s1 += v1[i];
        }
        s0 += __shfl_xor_sync(0xffffffffu, s0, 1);
        s0 += __shfl_xor_sync(0xffffffffu, s0, 2);
        s1 += __shfl_xor_sync(0xffffffffu, s1, 1);
        s1 += __shfl_xor_sync(0xffffffffu, s1, 2);
        float i0 = 1.0f / s0, i1 = 1.0f / s1;
        int ra = r0s + grp, rb = ra + 8;
        #pragma unroll
        for (int nt = 0; nt < 8; nt++) {
            *(__nv_bfloat162*)(sP + ra * LDP + nt * 8 + tig * 2) =
                __floats2bfloat162_rn(v0[2 * nt] * i0, v0[2 * nt + 1] * i0);
            *(__nv_bfloat162*)(sP + rb * LDP + nt * 8 + tig * 2) =
                __floats2bfloat162_rn(v1[2 * nt] * i1, v1[2 * nt + 1] * i1);
        }
    }
    __syncthreads();

    // ---------------- T = P @ X -> sK (K dead after S) ----------------
    {
        #pragma unroll
        for (int mt = 0; mt < 2; mt++)
            #pragma unroll
            for (int nt = 0; nt < 8; nt++)
                acc[mt][nt][0] = acc[mt][nt][1] = acc[mt][nt][2] = acc[mt][nt][3] = 0.f;
        #pragma unroll
        for (int ks = 0; ks < 4; ks++) {
            uint32_t a[2][4];
            #pragma unroll
            for (int mt = 0; mt < 2; mt++)
                ldm_x4(smem_u32(sP + (r0 + mt * 16 + (lane & 15)) * LDP
                                + ks * 16 + ((lane >> 4) << 3)),
                       a[mt][0], a[mt][1], a[mt][2], a[mt][3]);
            #pragma unroll
            for (int nt16 = 0; nt16 < 4; nt16++) {
                uint32_t b0, b1, b2, b3;
                ldm_x4t(smem_u32(sX + (ks * 16 + (lane & 15)) * LDH
                                 + nb + nt16 * 16 + ((lane >> 4) << 3)),
                        b0, b1, b2, b3);
                #pragma unroll
                for (int mt = 0; mt < 2; mt++) {
                    mma_bf16(acc[mt][2 * nt16],     a[mt][0], a[mt][1], a[mt][2], a[mt][3], b0, b1);
                    mma_bf16(acc[mt][2 * nt16 + 1], a[mt][0], a[mt][1], a[mt][2], a[mt][3], b2, b3);
                }
            }
        }
        #pragma unroll
        for (int mt = 0; mt < 2; mt++)
            #pragma unroll
            for (int nt = 0; nt < 8; nt++) {
                int col = nb + nt * 8 + tig * 2;
                int ra = r0 + mt * 16 + grp;
                *(__nv_bfloat162*)(sK + ra * LDH + col) =
                    __floats2bfloat162_rn(acc[mt][nt][0], acc[mt][nt][1]);
                *(__nv_bfloat162*)(sK + (ra + 8) * LDH + col) =
                    __floats2bfloat162_rn(acc[mt][nt][2], acc[mt][nt][3]);
            }
    }
    __syncthreads();

    // ---------------- O1 = T @ Wv + bv -> sX (X dead after T) ----------------
    gemm_w(g_Wb[2], sK, LDH, sW0, sW1, acc, tid, lane, r0, nb);
    #pragma unroll
    for (int mt = 0; mt < 2; mt++)
        #pragma unroll
        for (int nt = 0; nt < 8; nt++) {
            int col = nb + nt * 8 + tig * 2;
            float b0v = sBias[2 * CH + col], b1v = sBias[2 * CH + col + 1];
            int ra = r0 + mt * 16 + grp;
            *(__nv_bfloat162*)(sX + ra * LDH + col) =
                __floats2bfloat162_rn(acc[mt][nt][0] + b0v, acc[mt][nt][1] + b1v);
            *(__nv_bfloat162*)(sX + (ra + 8) * LDH + col) =
                __floats2bfloat162_rn(acc[mt][nt][2] + b0v, acc[mt][nt][3] + b1v);
        }
    __syncthreads();

    // ---------------- out = O1 @ Wo + bo + x ----------------
    gemm_w(g_Wb[3], sX, LDH, sW0, sW1, acc, tid, lane, r0, nb);
    #pragma unroll
    for (int mt = 0; mt < 2; mt++)
        #pragma unroll
        for (int nt = 0; nt < 8; nt++) {
            int col = nb + nt * 8 + tig * 2;
            float b0v = sBias[3 * CH + col], b1v = sBias[3 * CH + col + 1];
            int ra = r0 + mt * 16 + grp, rb = ra + 8;
            float2 xa = *(const float2*)(xrow + ra * CH + col);
            float2 xb = *(const float2*)(xrow + rb * CH + col);
            *(float2*)(orow + ra * CH + col) =
                make_float2(acc[mt][nt][0] + b0v + xa.x, acc[mt][nt][1] + b1v + xa.y);
            *(float2*)(orow + rb * CH + col) =
                make_float2(acc[mt][nt][2] + b0v + xb.x, acc[mt][nt][3] + b1v + xb.y);
        }
}

extern "C" void kernel_launch(void* const* d_in, const int* in_sizes, int n_in,
                              void* d_out, int out_size) {
    const float* x  = (const float*)d_in[0];
    const float* Wq = (const float*)d_in[1];
    const float* bq = (const float*)d_in[2];
    const float* Wk = (const float*)d_in[3];
    const float* bk = (const float*)d_in[4];
    const float* Wv = (const float*)d_in[5];
    const float* bv = (const float*)d_in[6];
    const float* Wo = (const float*)d_in[7];
    const float* bo = (const float*)d_in[8];
    float* out = (float*)d_out;

    convw_kernel<<<256, 256>>>(Wq, Wk, Wv, Wo);

    cudaFuncSetAttribute(attn_kernel, cudaFuncAttributeMaxDynamicSharedMemorySize, SMEM_BYTES);
    attn_kernel<<<2048, 256, SMEM_BYTES>>>(x, bq, bk, bv, bo, out);
}

// round 5
// speedup vs baseline: 1.7094x; 1.0828x over previous
#include <cuda_runtime.h>
#include <cuda_bf16.h>
#include <cstdint>

// AttentionBlock fused kernel, sm_103a. Round 4:
// Algebraic fusion: M8=Wq@Wk^T, W9=Wv@Wo precomputed; block becomes
//   G=X@M8; S=G@X^T(+c_j); P=softmax; T=P@X; out=T@W9+b9+x.
// Halves tensor FLOPs vs R3. mma.sync engine, 2 CTAs/SM.

#define SEQ   64
#define CH    256
#define LDH   264   // bf16 tile row stride in halves
#define LDP   72    // bf16 P tile stride

__device__ __nv_bfloat16 g_M8[CH * CH];   // Wq @ Wk^T   [a][b]
__device__ __nv_bfloat16 g_W9[CH * CH];   // Wv @ Wo     [a][b]
__device__ float g_b9[CH];                // bv @ Wo + bo
__device__ float g_w8[CH];                // Wk @ bq
__device__ float g_s8;                    // bk . bq

// ---- setup: fused weight products (fp32 accum, bf16 out) ----
__global__ void setup_gemm_kernel(const float* __restrict__ Wq, const float* __restrict__ Wk,
                                  const float* __restrict__ Wv, const float* __restrict__ Wo) {
    __shared__ float As[32][33];
    __shared__ float Bs[32][33];
    const int tid = threadIdx.x;
    const int tx = tid & 31, ty = tid >> 5;
    const int a0 = blockIdx.y * 32, b0 = blockIdx.x * 32;
    const int z = blockIdx.z;
    const float* A = z ? Wv : Wq;

    float acc[4] = {0.f, 0.f, 0.f, 0.f};
    for (int d0 = 0; d0 < CH; d0 += 32) {
        {   // stage A[i][j] = A[a0+i][d0+j]  (coalesced)
            int i = tid >> 3, j = (tid & 7) * 4;
            float4 v = *(const float4*)(A + (a0 + i) * CH + d0 + j);
            As[i][j] = v.x; As[i][j + 1] = v.y; As[i][j + 2] = v.z; As[i][j + 3] = v.w;
        }
        if (z == 0) {   // Bs[dd][c] = Wk[b0+c][d0+dd]
            int i = tid >> 3, j = (tid & 7) * 4;
            float4 v = *(const float4*)(Wk + (b0 + i) * CH + d0 + j);
            Bs[j][i] = v.x; Bs[j + 1][i] = v.y; Bs[j + 2][i] = v.z; Bs[j + 3][i] = v.w;
        } else {        // Bs[dd][c] = Wo[d0+dd][b0+c]
            int j = tid >> 3, i = (tid & 7) * 4;
            float4 v = *(const float4*)(Wo + (d0 + j) * CH + b0 + i);
            Bs[j][i] = v.x; Bs[j][i + 1] = v.y; Bs[j][i + 2] = v.z; Bs[j][i + 3] = v.w;
        }
        __syncthreads();
        #pragma unroll
        for (int dd = 0; dd < 32; dd++) {
            float b = Bs[dd][tx];
            #pragma unroll
            for (int r = 0; r < 4; r++)
                acc[r] += As[ty + 8 * r][dd] * b;
        }
        __syncthreads();
    }
    __nv_bfloat16* dst = z ? g_W9 : g_M8;
    #pragma unroll
    for (int r = 0; r < 4; r++)
        dst[(a0 + ty + 8 * r) * CH + b0 + tx] = __float2bfloat16(acc[r]);
}

__global__ void setup_vec_kernel(const float* __restrict__ Wk, const float* __restrict__ Wo,
                                 const float* __restrict__ bq, const float* __restrict__ bk,
                                 const float* __restrict__ bv, const float* __restrict__ bo) {
    int c = threadIdx.x;
    float w8 = 0.f, b9 = 0.f;
    for (int d = 0; d < CH; d++) {
        w8 += Wk[c * CH + d] * bq[d];
        b9 += bv[d] * Wo[d * CH + c];
    }
    g_w8[c] = w8;
    g_b9[c] = b9 + bo[c];
    if (c == 0) {
        float s = 0.f;
        for (int d = 0; d < CH; d++) s += bk[d] * bq[d];
        g_s8 = s;
    }
}

// ---- mma.sync helpers ----
__device__ __forceinline__ uint32_t smem_u32(const void* p) {
    return (uint32_t)__cvta_generic_to_shared(p);
}
__device__ __forceinline__ void ldm_x4(uint32_t addr, uint32_t& a0, uint32_t& a1,
                                       uint32_t& a2, uint32_t& a3) {
    asm volatile("ldmatrix.sync.aligned.m8n8.x4.shared.b16 {%0,%1,%2,%3}, [%4];"
                 : "=r"(a0), "=r"(a1), "=r"(a2), "=r"(a3) : "r"(addr));
}
__device__ __forceinline__ void ldm_x4t(uint32_t addr, uint32_t& b0, uint32_t& b1,
                                        uint32_t& b2, uint32_t& b3) {
    asm volatile("ldmatrix.sync.aligned.m8n8.x4.trans.shared.b16 {%0,%1,%2,%3}, [%4];"
                 : "=r"(b0), "=r"(b1), "=r"(b2), "=r"(b3) : "r"(addr));
}
__device__ __forceinline__ void mma_bf16(float c[4],
                                         uint32_t a0, uint32_t a1, uint32_t a2, uint32_t a3,
                                         uint32_t b0, uint32_t b1) {
    asm volatile("mma.sync.aligned.m16n8k16.row.col.f32.bf16.bf16.f32 "
                 "{%0,%1,%2,%3}, {%4,%5,%6,%7}, {%8,%9}, {%0,%1,%2,%3};"
                 : "+f"(c[0]), "+f"(c[1]), "+f"(c[2]), "+f"(c[3])
                 : "r"(a0), "r"(a1), "r"(a2), "r"(a3), "r"(b0), "r"(b1));
}
__device__ __forceinline__ void cp16(void* smem, const void* gmem) {
    asm volatile("cp.async.cg.shared.global [%0], [%1], 16;"
                 :: "r"(smem_u32(smem)), "l"(gmem));
}

// Stream a [32 k][256 n] bf16 weight chunk into smem (strided LDH rows).
__device__ __forceinline__ void load_w_chunk32(__nv_bfloat16* dst,
                                               const __nv_bfloat16* src, int tid) {
    #pragma unroll
    for (int i = 0; i < 4; i++) {
        int j = tid + i * 256;     // 1024 x 16B
        cp16(dst + (j >> 5) * LDH + (j & 31) * 8, src + j * 8);
    }
    asm volatile("cp.async.commit_group;");
}

// Core chunked GEMM: acc[32x64 warp tile] = A[64x256](smem) @ W[256x256](gmem).
__device__ __forceinline__ void gemm_w(const __nv_bfloat16* __restrict__ Wg,
                                       const __nv_bfloat16* sA, int ldA,
                                       __nv_bfloat16* sW0, __nv_bfloat16* sW1,
                                       float acc[2][8][4],
                                       int tid, int lane, int r0, int nb) {
    #pragma unroll
    for (int mt = 0; mt < 2; mt++)
        #pragma unroll
        for (int nt = 0; nt < 8; nt++)
            acc[mt][nt][0] = acc[mt][nt][1] = acc[mt][nt][2] = acc[mt][nt][3] = 0.f;

    load_w_chunk32(sW0, Wg, tid);
    #pragma unroll 1
    for (int kc = 0; kc < 8; kc++) {
        __nv_bfloat16* wbuf = (kc & 1) ? sW1 : sW0;
        if (kc < 7) {
            load_w_chunk32((kc & 1) ? sW0 : sW1, Wg + (kc + 1) * 32 * CH, tid);
            asm volatile("cp.async.wait_group 1;");
        } else {
            asm volatile("cp.async.wait_group 0;");
        }
        __syncthreads();
        #pragma unroll
        for (int ks = 0; ks < 2; ks++) {
            int kof = kc * 32 + ks * 16;
            uint32_t a[2][4];
            #pragma unroll
            for (int mt = 0; mt < 2; mt++)
                ldm_x4(smem_u32(sA + (r0 + mt * 16 + (lane & 15)) * ldA
                                + kof + ((lane >> 4) << 3)),
                       a[mt][0], a[mt][1], a[mt][2], a[mt][3]);
            #pragma unroll
            for (int nt16 = 0; nt16 < 4; nt16++) {
                uint32_t b0, b1, b2, b3;
                ldm_x4t(smem_u32(wbuf + (ks * 16 + (lane & 15)) * LDH
                                 + nb + nt16 * 16 + ((lane >> 4) << 3)),
                        b0, b1, b2, b3);
                #pragma unroll
                for (int mt = 0; mt < 2; mt++) {
                    mma_bf16(acc[mt][2 * nt16],     a[mt][0], a[mt][1], a[mt][2], a[mt][3], b0, b1);
                    mma_bf16(acc[mt][2 * nt16 + 1], a[mt][0], a[mt][1], a[mt][2], a[mt][3], b2, b3);
                }
            }
        }
        __syncthreads();
    }
}

// SMEM: sX 33792 + sG 33792 + sW0/sW1 33792 + sP 9216 + sC 256 + sBias 1024 = 111872
#define SMEM_BYTES 111872

__global__ void __launch_bounds__(256, 2)
attn_kernel(const float* __restrict__ x, float* __restrict__ out)
{
    extern __shared__ char smem_raw[];
    __nv_bfloat16* sX  = (__nv_bfloat16*)smem_raw;
    __nv_bfloat16* sG  = sX + SEQ * LDH;
    __nv_bfloat16* sW0 = sG + SEQ * LDH;
    __nv_bfloat16* sW1 = sW0 + 32 * LDH;
    __nv_bfloat16* sP  = sW1 + 32 * LDH;
    float*         sC  = (float*)(sP + SEQ * LDP);
    float*      sBias  = sC + SEQ;

    const int tid  = threadIdx.x;
    const int wid  = tid >> 5;
    const int lane = tid & 31;
    const int grp  = lane >> 2;
    const int tig  = lane & 3;
    const int bh   = blockIdx.x;

    const float* xrow = x   + (size_t)bh * SEQ * CH;
    float*       orow = out + (size_t)bh * SEQ * CH;

    // ---------------- Phase 0: bias + x tile (fp32 -> bf16) ----------------
    sBias[tid] = g_b9[tid];
    {
        const float4* xv = (const float4*)xrow;
        #pragma unroll
        for (int t = 0; t < 16; t++) {
            int i = tid + t * 256;             // 4096 float4
            int row = i >> 6;
            int colf = (i & 63) * 4;
            float4 v = xv[i];
            __nv_bfloat162* d = (__nv_bfloat162*)(sX + row * LDH + colf);
            d[0] = __floats2bfloat162_rn(v.x, v.y);
            d[1] = __floats2bfloat162_rn(v.z, v.w);
        }
    }
    __syncthreads();

    // c_j = x_j . w8 + s8  (column correction; zero when biases are zero)
    {
        int row = tid >> 2, q = tid & 3;
        const __nv_bfloat16* xr = sX + row * LDH + q * 64;
        float s = 0.f;
        #pragma unroll
        for (int e = 0; e < 64; e++) s += __bfloat162float(xr[e]) * g_w8[q * 64 + e];
        s += __shfl_xor_sync(0xffffffffu, s, 1);
        s += __shfl_xor_sync(0xffffffffu, s, 2);
        if (q == 0) sC[row] = s + g_s8;
    }
    // no sync needed yet: sC consumed after gemm_w's internal syncs

    const int r0 = (wid >> 2) * 32;   // warp's 32 rows (GEMM tiling)
    const int nb = (wid & 3) * 64;    // warp's 64 cols

    float acc[2][8][4];

    // ---------------- G = X @ M8 -> sG ----------------
    gemm_w(g_M8, sX, LDH, sW0, sW1, acc, tid, lane, r0, nb);
    #pragma unroll
    for (int mt = 0; mt < 2; mt++)
        #pragma unroll
        for (int nt = 0; nt < 8; nt++) {
            int col = nb + nt * 8 + tig * 2;
            int ra = r0 + mt * 16 + grp;
            *(__nv_bfloat162*)(sG + ra * LDH + col) =
                __floats2bfloat162_rn(acc[mt][nt][0], acc[mt][nt][1]);
            *(__nv_bfloat162*)(sG + (ra + 8) * LDH + col) =
                __floats2bfloat162_rn(acc[mt][nt][2], acc[mt][nt][3]);
        }
    __syncthreads();

    // ---------------- S = (G X^T + c_j)*scale, softmax -> P (warps 0-3) ----
    if (wid < 4) {
        const int r0s = wid * 16;     // 16 rows, all 64 cols
        float sa[8][4];
        #pragma unroll
        for (int nt = 0; nt < 8; nt++)
            sa[nt][0] = sa[nt][1] = sa[nt][2] = sa[nt][3] = 0.f;
        #pragma unroll
        for (int ks = 0; ks < 16; ks++) {
            uint32_t a0, a1, a2, a3;
            ldm_x4(smem_u32(sG + (r0s + (lane & 15)) * LDH + ks * 16 + ((lane >> 4) << 3)),
                   a0, a1, a2, a3);
            #pragma unroll
            for (int nt16 = 0; nt16 < 4; nt16++) {
                uint32_t b0, b1, b2, b3;
                // non-trans x4 on row-major X -> col-major B frags (k=channel)
                ldm_x4(smem_u32(sX + (nt16 * 16 + ((lane >> 4) << 3) + (lane & 7)) * LDH
                                + ks * 16 + (((lane >> 3) & 1) << 3)),
                       b0, b1, b2, b3);
                mma_bf16(sa[2 * nt16],     a0, a1, a2, a3, b0, b1);
                mma_bf16(sa[2 * nt16 + 1], a0, a1, a2, a3, b2, b3);
            }
        }
        const float SCALE = 1.0f / (256.0f * 16.0f * 0.70710678118654752f);
        float v0[16], v1[16];
        #pragma unroll
        for (int nt = 0; nt < 8; nt++) {
            int col = nt * 8 + tig * 2;
            float c0 = sC[col], c1 = sC[col + 1];
            v0[2 * nt] = (sa[nt][0] + c0) * SCALE; v0[2 * nt + 1] = (sa[nt][1] + c1) * SCALE;
            v1[2 * nt] = (sa[nt][2] + c0) * SCALE; v1[2 * nt + 1] = (sa[nt][3] + c1) * SCALE;
        }
        float m0 = v0[0], m1 = v1[0];
        #pragma unroll
        for (int i = 1; i < 16; i++) { m0 = fmaxf(m0, v0[i]); m1 = fmaxf(m1, v1[i]); }
        m0 = fmaxf(m0, __shfl_xor_sync(0xffffffffu, m0, 1));
        m0 = fmaxf(m0, __shfl_xor_sync(0xffffffffu, m0, 2));
        m1 = fmaxf(m1, __shfl_xor_sync(0xffffffffu, m1, 1));
        m1 = fmaxf(m1, __shfl_xor_sync(0xffffffffu, m1, 2));
        float s0 = 0.f, s1 = 0.f;
        #pragma unroll
        for (int i = 0; i < 16; i++) {
            v0[i] = __expf(v0[i] - m0); s0 += v0[i];
            v1[i] = __expf(v1[i] - m1); s1 += v1[i];
        }
        s0 += __shfl_xor_sync(0xffffffffu, s0, 1);
        s0 += __shfl_xor_sync(0xffffffffu, s0, 2);
        s1 += __shfl_xor_sync(0xffffffffu, s1, 1);
        s1 += __shfl_xor_sync(0xffffffffu, s1, 2);
        float i0 = 1.0f / s0, i1 = 1.0f / s1;
        int ra = r0s + grp, rb = ra + 8;
        #pragma unroll
        for (int nt = 0; nt < 8; nt++) {
            *(__nv_bfloat162*)(sP + ra * LDP + nt * 8 + tig * 2) =
                __floats2bfloat162_rn(v0[2 * nt] * i0, v0[2 * nt + 1] * i0);
            *(__nv_bfloat162*)(sP + rb * LDP + nt * 8 + tig * 2) =
                __floats2bfloat162_rn(v1[2 * nt] * i1, v1[2 * nt + 1] * i1);
        }
    }
    __syncthreads();

    // ---------------- T = P @ X -> sG (G dead after S) ----------------
    {
        #pragma unroll
        for (int mt = 0; mt < 2; mt++)
            #pragma unroll
            for (int nt = 0; nt < 8; nt++)
                acc[mt][nt][0] = acc[mt][nt][1] = acc[mt][nt][2] = acc[mt][nt][3] = 0.f;
        #pragma unroll
        for (int ks = 0; ks < 4; ks++) {
            uint32_t a[2][4];
            #pragma unroll
            for (int mt = 0; mt < 2; mt++)
                ldm_x4(smem_u32(sP + (r0 + mt * 16 + (lane & 15)) * LDP
                                + ks * 16 + ((lane >> 4) << 3)),
                       a[mt][0], a[mt][1], a[mt][2], a[mt][3]);
            #pragma unroll
            for (int nt16 = 0; nt16 < 4; nt16++) {
                uint32_t b0, b1, b2, b3;
                ldm_x4t(smem_u32(sX + (ks * 16 + (lane & 15)) * LDH
                                 + nb + nt16 * 16 + ((lane >> 4) << 3)),
                        b0, b1, b2, b3);
                #pragma unroll
                for (int mt = 0; mt < 2; mt++) {
                    mma_bf16(acc[mt][2 * nt16],     a[mt][0], a[mt][1], a[mt][2], a[mt][3], b0, b1);
                    mma_bf16(acc[mt][2 * nt16 + 1], a[mt][0], a[mt][1], a[mt][2], a[mt][3], b2, b3);
                }
            }
        }
        __syncthreads();   // all phase-B reads of sG complete
        #pragma unroll
        for (int mt = 0; mt < 2; mt++)
            #pragma unroll
            for (int nt = 0; nt < 8; nt++) {
                int col = nb + nt * 8 + tig * 2;
                int ra = r0 + mt * 16 + grp;
                *(__nv_bfloat162*)(sG + ra * LDH + col) =
                    __floats2bfloat162_rn(acc[mt][nt][0], acc[mt][nt][1]);
                *(__nv_bfloat162*)(sG + (ra + 8) * LDH + col) =
                    __floats2bfloat162_rn(acc[mt][nt][2], acc[mt][nt][3]);
            }
    }
    __syncthreads();

    // ---------------- out = T @ W9 + b9 + x ----------------
    gemm_w(g_W9, sG, LDH, sW0, sW1, acc, tid, lane, r0, nb);
    #pragma unroll
    for (int mt = 0; mt < 2; mt++)
        #pragma unroll
        for (int nt = 0; nt < 8; nt++) {
            int col = nb + nt * 8 + tig * 2;
            float b0v = sBias[col], b1v = sBias[col + 1];
            int ra = r0 + mt * 16 + grp, rb = ra + 8;
            float2 xa = *(const float2*)(xrow + ra * CH + col);
            float2 xb = *(const float2*)(xrow + rb * CH + col);
            *(float2*)(orow + ra * CH + col) =
                make_float2(acc[mt][nt][0] + b0v + xa.x, acc[mt][nt][1] + b1v + xa.y);
            *(float2*)(orow + rb * CH + col) =
                make_float2(acc[mt][nt][2] + b0v + xb.x, acc[mt][nt][3] + b1v + xb.y);
        }
}

extern "C" void kernel_launch(void* const* d_in, const int* in_sizes, int n_in,
                              void* d_out, int out_size) {
    const float* x  = (const float*)d_in[0];
    const float* Wq = (const float*)d_in[1];
    const float* bq = (const float*)d_in[2];
    const float* Wk = (const float*)d_in[3];
    const float* bk = (const float*)d_in[4];
    const float* Wv = (const float*)d_in[5];
    const float* bv = (const float*)d_in[6];
    const float* Wo = (const float*)d_in[7];
    const float* bo = (const float*)d_in[8];
    float* out = (float*)d_out;

    dim3 g8(8, 8, 2);
    setup_gemm_kernel<<<g8, 256>>>(Wq, Wk, Wv, Wo);
    setup_vec_kernel<<<1, 256>>>(Wk, Wo, bq, bk, bv, bo);

    cudaFuncSetAttribute(attn_kernel, cudaFuncAttributeMaxDynamicSharedMemorySize, SMEM_BYTES);
    attn_kernel<<<2048, 256, SMEM_BYTES>>>(x, out);
}